// round 10
// baseline (speedup 1.0000x reference)
#include <cuda_runtime.h>
#include <cuda_fp16.h>
#include <cstdint>

// LocalAtomAttention (round 10): mma.sync fp16; B-operand fragments pre-swizzled
// in GLOBAL memory (L1-cached LDG.128) -- no W smem staging, no cp.async.
// smem/CTA = 52.7KB (X, Q, K tiles + masks), 2 CTAs/SM, L1D ~122KB holds W.
// Phases (5 syncthreads): X load | Q gemm, K gemm, V gemm | V->XH | attn |
// Y->QHO | O gemm -> gmem.

namespace laa {
constexpr int C = 128, TOKS = 64, NT = 256;
constexpr uint32_t RS = 272;            // smem row stride bytes
constexpr uint32_t XH = 0, QHO = 17408, KHO = 34816,
                   MSK = 52224, RM = 52480, TOTAL = 52736;
constexpr float SCALE = 0.17677669529663687f;  // 1/sqrt(32)
}

// Fragment-ordered W images: per matrix [T(8)][ks(8)][lane(32)] x 16B = 32KB.
// reg r of lane l = half2{ W[n][k], W[n][k+1] },
//   n = T*16 + (r>=2)*8 + (l>>2),  k = ks*16 + (r&1)*8 + 2*(l&3).
__device__ __align__(16) uint32_t g_wfrag[4][8192];
__device__ float g_bias[4][128];   // {bq*s, bk, bv, bo}

// ---------------- helpers ----------------
__device__ __forceinline__ uint32_t smem_u32(const void* p) {
    uint32_t a;
    asm("{ .reg .u64 t; cvta.to.shared.u64 t, %1; cvt.u32.u64 %0, t; }" : "=r"(a) : "l"(p));
    return a;
}
__device__ __forceinline__ void ldsm4(uint32_t& a0, uint32_t& a1, uint32_t& a2,
                                      uint32_t& a3, uint32_t addr) {
    asm volatile("ldmatrix.sync.aligned.m8n8.x4.shared.b16 {%0,%1,%2,%3}, [%4];"
                 : "=r"(a0), "=r"(a1), "=r"(a2), "=r"(a3) : "r"(addr));
}
__device__ __forceinline__ void mma16816(float d[4], uint32_t a0, uint32_t a1,
                                         uint32_t a2, uint32_t a3,
                                         uint32_t b0, uint32_t b1) {
    asm volatile(
        "mma.sync.aligned.m16n8k16.row.col.f32.f16.f16.f32 "
        "{%0,%1,%2,%3}, {%4,%5,%6,%7}, {%8,%9}, {%0,%1,%2,%3};"
        : "+f"(d[0]), "+f"(d[1]), "+f"(d[2]), "+f"(d[3])
        : "r"(a0), "r"(a1), "r"(a2), "r"(a3), "r"(b0), "r"(b1));
}

// ---------------- prep kernel: build fragment images (32 blocks) ----------------
__global__ void prep_frag(const float* __restrict__ Wq, const float* __restrict__ bq,
                          const float* __restrict__ Wk, const float* __restrict__ bk,
                          const float* __restrict__ Wv, const float* __restrict__ bv,
                          const float* __restrict__ Wo, const float* __restrict__ bo) {
    const int m = blockIdx.x >> 3;            // matrix
    const int chunk = blockIdx.x & 7;         // 8 chunks of 256 uint4
    const float* src  = (m == 0) ? Wq : (m == 1) ? Wk : (m == 2) ? Wv : Wo;
    const float* bsrc = (m == 0) ? bq : (m == 1) ? bk : (m == 2) ? bv : bo;
    const float sc = (m == 0) ? laa::SCALE : 1.f;

    const int e = chunk * 256 + threadIdx.x;  // uint4 index 0..2047
    const int l = e & 31, ks = (e >> 5) & 7, T = e >> 8;
    uint32_t regs[4];
#pragma unroll
    for (int r = 0; r < 4; ++r) {
        const int n = T * 16 + (r >> 1) * 8 + (l >> 2);
        const int k = ks * 16 + (r & 1) * 8 + 2 * (l & 3);
        __half2 h = __floats2half2_rn(src[n * 128 + k] * sc, src[n * 128 + k + 1] * sc);
        regs[r] = *(uint32_t*)&h;
    }
    *((uint4*)g_wfrag[m] + e) = *(uint4*)regs;
    if (chunk == 0 && threadIdx.x < 128)
        g_bias[m][threadIdx.x] = bsrc[threadIdx.x] * sc;
}

// ---------------- main kernel ----------------
using namespace laa;

// Warp GEMM: D[32 rows x 32 cols] += A·B^T over K=128; A from smem (ldsm),
// B fragments from global image (LDG.128, L1-cached).
__device__ __forceinline__ void warp_gemm32(uint32_t a_t, const uint4* wfrag,
                                            int r0, int nc0, float d[2][4][4],
                                            int lane) {
    const uint32_t aoff = (uint32_t)(r0 + (lane & 15)) * RS + ((lane >> 4) << 4);
    const uint4* bp = wfrag + (uint32_t)(nc0 >> 4) * 256 + lane;
#pragma unroll
    for (int ks = 0; ks < 8; ++ks) {
        const uint32_t kb = ks * 32;
        uint32_t a0, a1, a2, a3, a4, a5, a6, a7;
        ldsm4(a0, a1, a2, a3, a_t + aoff + kb);
        ldsm4(a4, a5, a6, a7, a_t + aoff + 16 * RS + kb);
#pragma unroll
        for (int np = 0; np < 2; ++np) {
            const uint4 b = __ldg(bp + np * 256 + ks * 32);
            mma16816(d[0][2 * np],     a0, a1, a2, a3, b.x, b.y);
            mma16816(d[0][2 * np + 1], a0, a1, a2, a3, b.z, b.w);
            mma16816(d[1][2 * np],     a4, a5, a6, a7, b.x, b.y);
            mma16816(d[1][2 * np + 1], a4, a5, a6, a7, b.z, b.w);
        }
    }
}

__global__ __launch_bounds__(NT, 2)
void laa_mma_kernel(const float* __restrict__ x, const int* __restrict__ mask,
                    float* __restrict__ out)
{
    extern __shared__ __align__(16) char sm[];
    const uint32_t sb = smem_u32(sm);
    const int tid = threadIdx.x, lane = tid & 31, w = tid >> 5;
    const long long tok0 = (long long)blockIdx.x * TOKS;

    float* msk_f = (float*)(sm + MSK);
    float* rm_f  = (float*)(sm + RM);

    // ---- P0: X load + fp16 convert; masks ----
#pragma unroll
    for (int it = 0; it < 8; ++it) {
        int idx = it * NT + tid;              // float4 index over [64][32]
        int row = idx >> 5, c4 = idx & 31;
        float4 v = __ldg((const float4*)x + (tok0 + row) * 32 + c4);
        __half2 h01 = __floats2half2_rn(v.x, v.y);
        __half2 h23 = __floats2half2_rn(v.z, v.w);
        uint2 hv;
        hv.x = *(uint32_t*)&h01; hv.y = *(uint32_t*)&h23;
        *(uint2*)(sm + XH + row * RS + c4 * 8) = hv;
    }
    if (tid < TOKS) {
        msk_f[tid] = (__ldg(&mask[tok0 + tid]) != 0) ? 1.f : 0.f;
        long long b = tok0 + (tid & ~3);
        int any = __ldg(&mask[b]) | __ldg(&mask[b + 1]) | __ldg(&mask[b + 2]) | __ldg(&mask[b + 3]);
        rm_f[tid] = (any != 0) ? 1.f : 0.f;
    }
    __syncthreads();                          // (1) X visible

    const int r0 = (w >> 2) * 32;             // {0,32}
    const int nc0 = (w & 3) * 32;             // {0,32,64,96}
    const int rq = lane >> 2;
    const int c2 = 2 * (lane & 3);

    // ---- P1: Q GEMM -> QHO; K GEMM -> KHO; V GEMM (accums held) ----
    {
        float d[2][4][4] = {};
        warp_gemm32(sb + XH, (const uint4*)g_wfrag[0], r0, nc0, d, lane);
#pragma unroll
        for (int mi = 0; mi < 2; ++mi) {
            const int ra = r0 + mi * 16 + rq, rb = ra + 8;
#pragma unroll
            for (int j = 0; j < 4; ++j) {
                const int col = nc0 + (j >> 1) * 16 + (j & 1) * 8 + c2;
                const float b0 = g_bias[0][col], b1 = g_bias[0][col + 1];
                *(__half2*)(sm + QHO + ra * RS + col * 2) =
                    __floats2half2_rn(d[mi][j][0] + b0, d[mi][j][1] + b1);
                *(__half2*)(sm + QHO + rb * RS + col * 2) =
                    __floats2half2_rn(d[mi][j][2] + b0, d[mi][j][3] + b1);
            }
        }
    }
    {
        float d[2][4][4] = {};
        warp_gemm32(sb + XH, (const uint4*)g_wfrag[1], r0, nc0, d, lane);
#pragma unroll
        for (int mi = 0; mi < 2; ++mi) {
            const int ra = r0 + mi * 16 + rq, rb = ra + 8;
#pragma unroll
            for (int j = 0; j < 4; ++j) {
                const int col = nc0 + (j >> 1) * 16 + (j & 1) * 8 + c2;
                const float b0 = g_bias[1][col], b1 = g_bias[1][col + 1];
                *(__half2*)(sm + KHO + ra * RS + col * 2) =
                    __floats2half2_rn(d[mi][j][0] + b0, d[mi][j][1] + b1);
                *(__half2*)(sm + KHO + rb * RS + col * 2) =
                    __floats2half2_rn(d[mi][j][2] + b0, d[mi][j][3] + b1);
            }
        }
    }
    {
        float d[2][4][4] = {};
        warp_gemm32(sb + XH, (const uint4*)g_wfrag[2], r0, nc0, d, lane);
        __syncthreads();                      // (2) all X reads done
#pragma unroll
        for (int mi = 0; mi < 2; ++mi) {
            const int ra = r0 + mi * 16 + rq, rb = ra + 8;
#pragma unroll
            for (int j = 0; j < 4; ++j) {
                const int col = nc0 + (j >> 1) * 16 + (j & 1) * 8 + c2;
                const float b0 = g_bias[2][col], b1 = g_bias[2][col + 1];
                *(__half2*)(sm + XH + ra * RS + col * 2) =
                    __floats2half2_rn(d[mi][j][0] + b0, d[mi][j][1] + b1);
                *(__half2*)(sm + XH + rb * RS + col * 2) =
                    __floats2half2_rn(d[mi][j][2] + b0, d[mi][j][3] + b1);
            }
        }
    }
    __syncthreads();                          // (3) V (in XH), Q, K visible

    // ---- P2: attention, one unit per thread (res, h, qa); y = P·v_head ----
    float y[32];
    int tq, hh;
    {
        const int res = tid >> 4;
        hh = (tid >> 2) & 3;
        const int qa = tid & 3;
        tq = res * 4 + qa;

        float q[32];
#pragma unroll
        for (int i = 0; i < 4; ++i) {
            uint4 u = *(const uint4*)(sm + QHO + tq * RS + hh * 64 + i * 16);
            float2 f0 = __half22float2(*(__half2*)&u.x);
            float2 f1 = __half22float2(*(__half2*)&u.y);
            float2 f2 = __half22float2(*(__half2*)&u.z);
            float2 f3 = __half22float2(*(__half2*)&u.w);
            q[i * 8 + 0] = f0.x; q[i * 8 + 1] = f0.y; q[i * 8 + 2] = f1.x; q[i * 8 + 3] = f1.y;
            q[i * 8 + 4] = f2.x; q[i * 8 + 5] = f2.y; q[i * 8 + 6] = f3.x; q[i * 8 + 7] = f3.y;
        }
        float s[4];
#pragma unroll
        for (int ka = 0; ka < 4; ++ka) {
            float acc = 0.f;
            const char* kp = sm + KHO + (res * 4 + ka) * RS + hh * 64;
#pragma unroll
            for (int i = 0; i < 4; ++i) {
                uint4 u = *(const uint4*)(kp + i * 16);
                float2 f0 = __half22float2(*(__half2*)&u.x);
                float2 f1 = __half22float2(*(__half2*)&u.y);
                float2 f2 = __half22float2(*(__half2*)&u.z);
                float2 f3 = __half22float2(*(__half2*)&u.w);
                acc = fmaf(q[i * 8 + 0], f0.x, acc); acc = fmaf(q[i * 8 + 1], f0.y, acc);
                acc = fmaf(q[i * 8 + 2], f1.x, acc); acc = fmaf(q[i * 8 + 3], f1.y, acc);
                acc = fmaf(q[i * 8 + 4], f2.x, acc); acc = fmaf(q[i * 8 + 5], f2.y, acc);
                acc = fmaf(q[i * 8 + 6], f3.x, acc); acc = fmaf(q[i * 8 + 7], f3.y, acc);
            }
            s[ka] = (msk_f[res * 4 + ka] != 0.f) ? acc : -1e30f;
        }
        const float mx = fmaxf(fmaxf(s[0], s[1]), fmaxf(s[2], s[3]));
        float p[4], ps = 0.f;
#pragma unroll
        for (int ka = 0; ka < 4; ++ka) { p[ka] = __expf(s[ka] - mx); ps += p[ka]; }
        const float inv = 1.f / ps;

#pragma unroll
        for (int d = 0; d < 32; ++d) y[d] = 0.f;
#pragma unroll
        for (int ka = 0; ka < 4; ++ka) {
            const float pw = p[ka] * inv;
            const char* vp = sm + XH + (res * 4 + ka) * RS + hh * 64;
#pragma unroll
            for (int i = 0; i < 4; ++i) {
                uint4 u = *(const uint4*)(vp + i * 16);
                float2 f0 = __half22float2(*(__half2*)&u.x);
                float2 f1 = __half22float2(*(__half2*)&u.y);
                float2 f2 = __half22float2(*(__half2*)&u.z);
                float2 f3 = __half22float2(*(__half2*)&u.w);
                y[i * 8 + 0] = fmaf(pw, f0.x, y[i * 8 + 0]);
                y[i * 8 + 1] = fmaf(pw, f0.y, y[i * 8 + 1]);
                y[i * 8 + 2] = fmaf(pw, f1.x, y[i * 8 + 2]);
                y[i * 8 + 3] = fmaf(pw, f1.y, y[i * 8 + 3]);
                y[i * 8 + 4] = fmaf(pw, f2.x, y[i * 8 + 4]);
                y[i * 8 + 5] = fmaf(pw, f2.y, y[i * 8 + 5]);
                y[i * 8 + 6] = fmaf(pw, f3.x, y[i * 8 + 6]);
                y[i * 8 + 7] = fmaf(pw, f3.y, y[i * 8 + 7]);
            }
        }
    }
    __syncthreads();                          // (4) Q reads done before Y overwrite

    // ---- write Y fp16 -> QHO ----
    {
#pragma unroll
        for (int i = 0; i < 4; ++i) {
            uint4 hv;
            uint32_t* hp = &hv.x;
#pragma unroll
            for (int gidx = 0; gidx < 4; ++gidx) {
                __half2 h = __floats2half2_rn(y[i * 8 + gidx * 2], y[i * 8 + gidx * 2 + 1]);
                hp[gidx] = *(uint32_t*)&h;
            }
            *(uint4*)(sm + QHO + tq * RS + hh * 64 + i * 16) = hv;
        }
    }
    __syncthreads();                          // (5) Y visible

    // ---- P3: O GEMM (A=Y in QHO): out = Y·Wo^T + bo, × residue mask ----
    {
        float d[2][4][4] = {};
        warp_gemm32(sb + QHO, (const uint4*)g_wfrag[3], r0, nc0, d, lane);
#pragma unroll
        for (int mi = 0; mi < 2; ++mi) {
            const int ra = r0 + mi * 16 + rq, rb = ra + 8;
            const float rma = rm_f[ra], rmb = rm_f[rb];
#pragma unroll
            for (int j = 0; j < 4; ++j) {
                const int col = nc0 + (j >> 1) * 16 + (j & 1) * 8 + c2;
                const float b0 = g_bias[3][col], b1 = g_bias[3][col + 1];
                float2 va, vb;
                va.x = (d[mi][j][0] + b0) * rma; va.y = (d[mi][j][1] + b1) * rma;
                vb.x = (d[mi][j][2] + b0) * rmb; vb.y = (d[mi][j][3] + b1) * rmb;
                *(float2*)(out + (tok0 + ra) * C + col) = va;
                *(float2*)(out + (tok0 + rb) * C + col) = vb;
            }
        }
    }
}

extern "C" void kernel_launch(void* const* d_in, const int* in_sizes, int n_in,
                              void* d_out, int out_size)
{
    const float* x    = (const float*)d_in[0];
    const int*   mask = (const int*)d_in[1];
    const float* Wq = (const float*)d_in[2];
    const float* bq = (const float*)d_in[3];
    const float* Wk = (const float*)d_in[4];
    const float* bk = (const float*)d_in[5];
    const float* Wv = (const float*)d_in[6];
    const float* bv = (const float*)d_in[7];
    const float* Wo = (const float*)d_in[8];
    const float* bo = (const float*)d_in[9];
    float* out = (float*)d_out;

    const int ntok = in_sizes[0] / laa::C;      // 262144
    const int nblk = ntok / laa::TOKS;          // 4096

    prep_frag<<<32, 256>>>(Wq, bq, Wk, bk, Wv, bv, Wo, bo);

    cudaFuncSetAttribute(laa_mma_kernel,
                         cudaFuncAttributeMaxDynamicSharedMemorySize, laa::TOTAL);
    laa_mma_kernel<<<nblk, laa::NT, laa::TOTAL>>>(x, mask, out);
}

// round 11
// speedup vs baseline: 1.3270x; 1.3270x over previous
#include <cuda_runtime.h>
#include <cuda_fp16.h>
#include <cstdint>

// LocalAtomAttention (round 11): round-9 structure + A-fragment register
// caching across Q/K/V GEMMs + widened prep. mma.sync fp16, 32x32 warp tiles,
// W staged to smem (cp.async) into dead regions, 64-tok CTAs, 2 CTAs/SM.

namespace laa {
constexpr int C = 128, TOKS = 64, NT = 256;
constexpr uint32_t RS = 272;            // smem row stride bytes
constexpr uint32_t XH = 0, QHO = 17408, KHO = 34816 /*Wk then K*/,
                   W = 69632, MSK = 104448, RM = 104704,
                   TOTAL = 104960;      // x2 CTAs = 209,920 <= 228KB/SM
constexpr float SCALE = 0.17677669529663687f;  // 1/sqrt(32)
}

// Prepped fp16 weights: [4] = {Wq*s, Wk, Wv, Wo}, 272B rows, 34816B each.
__device__ __align__(16) unsigned char g_wimg[4][34816];
__device__ float g_bias[4][128];   // {bq*s, bk, bv, bo}

// ---------------- helpers ----------------
__device__ __forceinline__ uint32_t smem_u32(const void* p) {
    uint32_t a;
    asm("{ .reg .u64 t; cvta.to.shared.u64 t, %1; cvt.u32.u64 %0, t; }" : "=r"(a) : "l"(p));
    return a;
}
__device__ __forceinline__ void ldsm4(uint32_t& a0, uint32_t& a1, uint32_t& a2,
                                      uint32_t& a3, uint32_t addr) {
    asm volatile("ldmatrix.sync.aligned.m8n8.x4.shared.b16 {%0,%1,%2,%3}, [%4];"
                 : "=r"(a0), "=r"(a1), "=r"(a2), "=r"(a3) : "r"(addr));
}
__device__ __forceinline__ void mma16816(float d[4], uint32_t a0, uint32_t a1,
                                         uint32_t a2, uint32_t a3,
                                         uint32_t b0, uint32_t b1) {
    asm volatile(
        "mma.sync.aligned.m16n8k16.row.col.f32.f16.f16.f32 "
        "{%0,%1,%2,%3}, {%4,%5,%6,%7}, {%8,%9}, {%0,%1,%2,%3};"
        : "+f"(d[0]), "+f"(d[1]), "+f"(d[2]), "+f"(d[3])
        : "r"(a0), "r"(a1), "r"(a2), "r"(a3), "r"(b0), "r"(b1));
}
__device__ __forceinline__ void cpa16(uint32_t dst, const unsigned char* src) {
    uint64_t g;
    asm("cvta.to.global.u64 %0, %1;" : "=l"(g) : "l"(src));
    asm volatile("cp.async.cg.shared.global [%0], [%1], 16;" :: "r"(dst), "l"(g));
}
#define CPA_COMMIT() asm volatile("cp.async.commit_group;" ::: "memory")
#define CPA_WAIT0()  asm volatile("cp.async.wait_group 0;" ::: "memory")

// ---------------- prep kernel (32 blocks: 4 matrices x 8 chunks) ----------------
__global__ void prep_split(const float* __restrict__ Wq, const float* __restrict__ bq,
                           const float* __restrict__ Wk, const float* __restrict__ bk,
                           const float* __restrict__ Wv, const float* __restrict__ bv,
                           const float* __restrict__ Wo, const float* __restrict__ bo) {
    const int m = blockIdx.x >> 3;
    const int chunk = blockIdx.x & 7;
    const float* src  = (m == 0) ? Wq : (m == 1) ? Wk : (m == 2) ? Wv : Wo;
    const float* bsrc = (m == 0) ? bq : (m == 1) ? bk : (m == 2) ? bv : bo;
    const float sc = (m == 0) ? laa::SCALE : 1.f;
    unsigned char* img = g_wimg[m];
    for (int i = chunk * 2048 + threadIdx.x; i < (chunk + 1) * 2048; i += blockDim.x) {
        int row = i >> 7, col = i & 127;
        *(__half*)(img + row * laa::RS + col * 2) = __float2half_rn(src[i] * sc);
    }
    if (chunk == 0 && threadIdx.x < 128)
        g_bias[m][threadIdx.x] = bsrc[threadIdx.x] * sc;
}

// ---------------- main kernel ----------------
using namespace laa;

// Load A fragments for a 32-row warp tile over K=128: 16 ldsm4 -> 64 regs.
__device__ __forceinline__ void load_a(uint32_t a_t, int r0, int lane, uint32_t* af) {
    const uint32_t aoff = (uint32_t)(r0 + (lane & 15)) * RS + ((lane >> 4) << 4);
#pragma unroll
    for (int ks = 0; ks < 8; ++ks) {
        ldsm4(af[ks*8+0], af[ks*8+1], af[ks*8+2], af[ks*8+3], a_t + aoff + ks * 32);
        ldsm4(af[ks*8+4], af[ks*8+5], af[ks*8+6], af[ks*8+7], a_t + aoff + 16 * RS + ks * 32);
    }
}

// Warp GEMM with cached A: D[32x32] += A·B^T, B fragments via ldsm from smem.
__device__ __forceinline__ void warp_gemm_c(const uint32_t* af, uint32_t wbuf,
                                            int nc0, float d[2][4][4], int lane) {
    const uint32_t brow = (lane & 7) + ((lane & 16) >> 1);
    const uint32_t bkof = (lane & 8) << 1;
#pragma unroll
    for (int ks = 0; ks < 8; ++ks) {
        const uint32_t kb = ks * 32;
        const uint32_t* a = af + ks * 8;
#pragma unroll
        for (int np = 0; np < 2; ++np) {
            const uint32_t ba = (uint32_t)(nc0 + np * 16 + brow) * RS + bkof + kb;
            uint32_t b0, b1, b2, b3;
            ldsm4(b0, b1, b2, b3, wbuf + ba);
            mma16816(d[0][2 * np],     a[0], a[1], a[2], a[3], b0, b1);
            mma16816(d[0][2 * np + 1], a[0], a[1], a[2], a[3], b2, b3);
            mma16816(d[1][2 * np],     a[4], a[5], a[6], a[7], b0, b1);
            mma16816(d[1][2 * np + 1], a[4], a[5], a[6], a[7], b2, b3);
        }
    }
}

// Stage full W matrix m (34816 B) into dst via cp.async.
__device__ __forceinline__ void stage_w(uint32_t dst, int m, int tid) {
    const unsigned char* src = g_wimg[m];
#pragma unroll 2
    for (int i = tid; i < 2176; i += NT) cpa16(dst + i * 16, src + i * 16);
    CPA_COMMIT();
}

__global__ __launch_bounds__(NT, 2)
void laa_mma_kernel(const float* __restrict__ x, const int* __restrict__ mask,
                    float* __restrict__ out)
{
    extern __shared__ __align__(16) char sm[];
    const uint32_t sb = smem_u32(sm);
    const int tid = threadIdx.x, lane = tid & 31, w = tid >> 5;
    const long long tok0 = (long long)blockIdx.x * TOKS;

    float* msk_f = (float*)(sm + MSK);
    float* rm_f  = (float*)(sm + RM);

    // ---- P-1: stage Wq->W and Wk->KHO; X load + fp16 convert; masks ----
    stage_w(sb + W, 0, tid);
    stage_w(sb + KHO, 1, tid);
#pragma unroll
    for (int it = 0; it < 8; ++it) {
        int idx = it * NT + tid;              // float4 index over [64][32]
        int row = idx >> 5, c4 = idx & 31;
        float4 v = __ldg((const float4*)x + (tok0 + row) * 32 + c4);
        __half2 h01 = __floats2half2_rn(v.x, v.y);
        __half2 h23 = __floats2half2_rn(v.z, v.w);
        uint2 hv;
        hv.x = *(uint32_t*)&h01; hv.y = *(uint32_t*)&h23;
        *(uint2*)(sm + XH + row * RS + c4 * 8) = hv;
    }
    if (tid < TOKS) {
        msk_f[tid] = (__ldg(&mask[tok0 + tid]) != 0) ? 1.f : 0.f;
        long long b = tok0 + (tid & ~3);
        int any = __ldg(&mask[b]) | __ldg(&mask[b + 1]) | __ldg(&mask[b + 2]) | __ldg(&mask[b + 3]);
        rm_f[tid] = (any != 0) ? 1.f : 0.f;
    }
    CPA_WAIT0();
    __syncthreads();                          // (1) X, Wq, Wk visible

    const int r0 = (w >> 2) * 32;             // {0,32}
    const int nc0 = (w & 3) * 32;             // {0,32,64,96}
    const int rq = lane >> 2;
    const int c2 = 2 * (lane & 3);

    // ---- cache A fragments of X once (reused by Q, K, V GEMMs) ----
    uint32_t af[64];
    load_a(sb + XH, r0, lane, af);

    // ---- P0: Q GEMM (B=Wq in W) -> QHO fp16 ----
    {
        float d[2][4][4] = {};
        warp_gemm_c(af, sb + W, nc0, d, lane);
#pragma unroll
        for (int mi = 0; mi < 2; ++mi) {
            const int ra = r0 + mi * 16 + rq, rb = ra + 8;
#pragma unroll
            for (int j = 0; j < 4; ++j) {
                const int col = nc0 + (j >> 1) * 16 + (j & 1) * 8 + c2;
                const float b0 = g_bias[0][col], b1 = g_bias[0][col + 1];
                *(__half2*)(sm + QHO + ra * RS + col * 2) =
                    __floats2half2_rn(d[mi][j][0] + b0, d[mi][j][1] + b1);
                *(__half2*)(sm + QHO + rb * RS + col * 2) =
                    __floats2half2_rn(d[mi][j][2] + b0, d[mi][j][3] + b1);
            }
        }
    }
    __syncthreads();                          // (2) Wq reads done

    // ---- P1: stage Wv->W; K GEMM (B=Wk in KHO); write K->KHO ----
    stage_w(sb + W, 2, tid);
    {
        float d[2][4][4] = {};
        warp_gemm_c(af, sb + KHO, nc0, d, lane);
        __syncthreads();                      // (3) all Wk reads done
#pragma unroll
        for (int mi = 0; mi < 2; ++mi) {
            const int ra = r0 + mi * 16 + rq, rb = ra + 8;
#pragma unroll
            for (int j = 0; j < 4; ++j) {
                const int col = nc0 + (j >> 1) * 16 + (j & 1) * 8 + c2;
                const float b0 = g_bias[1][col], b1 = g_bias[1][col + 1];
                *(__half2*)(sm + KHO + ra * RS + col * 2) =
                    __floats2half2_rn(d[mi][j][0] + b0, d[mi][j][1] + b1);
                *(__half2*)(sm + KHO + rb * RS + col * 2) =
                    __floats2half2_rn(d[mi][j][2] + b0, d[mi][j][3] + b1);
            }
        }
    }
    CPA_WAIT0();                              // Wv staged
    __syncthreads();                          // (4) K visible, Wv ready

    // ---- P2: V GEMM (B=Wv in W); stage Wo; write V->XH (X dead: A cached) ----
    {
        float d[2][4][4] = {};
        warp_gemm_c(af, sb + W, nc0, d, lane);
        __syncthreads();                      // (5) Wv reads done
        stage_w(sb + W, 3, tid);              // Wo staging hides behind attention
#pragma unroll
        for (int mi = 0; mi < 2; ++mi) {
            const int ra = r0 + mi * 16 + rq, rb = ra + 8;
#pragma unroll
            for (int j = 0; j < 4; ++j) {
                const int col = nc0 + (j >> 1) * 16 + (j & 1) * 8 + c2;
                const float b0 = g_bias[2][col], b1 = g_bias[2][col + 1];
                *(__half2*)(sm + XH + ra * RS + col * 2) =
                    __floats2half2_rn(d[mi][j][0] + b0, d[mi][j][1] + b1);
                *(__half2*)(sm + XH + rb * RS + col * 2) =
                    __floats2half2_rn(d[mi][j][2] + b0, d[mi][j][3] + b1);
            }
        }
    }
    __syncthreads();                          // (6) V visible

    // ---- P3: attention, one unit per thread (res, h, qa); y = P·v_head ----
    float y[32];
    int tq, hh;
    {
        const int res = tid >> 4;
        hh = (tid >> 2) & 3;
        const int qa = tid & 3;
        tq = res * 4 + qa;

        float q[32];
#pragma unroll
        for (int i = 0; i < 4; ++i) {
            uint4 u = *(const uint4*)(sm + QHO + tq * RS + hh * 64 + i * 16);
            float2 f0 = __half22float2(*(__half2*)&u.x);
            float2 f1 = __half22float2(*(__half2*)&u.y);
            float2 f2 = __half22float2(*(__half2*)&u.z);
            float2 f3 = __half22float2(*(__half2*)&u.w);
            q[i * 8 + 0] = f0.x; q[i * 8 + 1] = f0.y; q[i * 8 + 2] = f1.x; q[i * 8 + 3] = f1.y;
            q[i * 8 + 4] = f2.x; q[i * 8 + 5] = f2.y; q[i * 8 + 6] = f3.x; q[i * 8 + 7] = f3.y;
        }
        float s[4];
#pragma unroll
        for (int ka = 0; ka < 4; ++ka) {
            float acc = 0.f;
            const char* kp = sm + KHO + (res * 4 + ka) * RS + hh * 64;
#pragma unroll
            for (int i = 0; i < 4; ++i) {
                uint4 u = *(const uint4*)(kp + i * 16);
                float2 f0 = __half22float2(*(__half2*)&u.x);
                float2 f1 = __half22float2(*(__half2*)&u.y);
                float2 f2 = __half22float2(*(__half2*)&u.z);
                float2 f3 = __half22float2(*(__half2*)&u.w);
                acc = fmaf(q[i * 8 + 0], f0.x, acc); acc = fmaf(q[i * 8 + 1], f0.y, acc);
                acc = fmaf(q[i * 8 + 2], f1.x, acc); acc = fmaf(q[i * 8 + 3], f1.y, acc);
                acc = fmaf(q[i * 8 + 4], f2.x, acc); acc = fmaf(q[i * 8 + 5], f2.y, acc);
                acc = fmaf(q[i * 8 + 6], f3.x, acc); acc = fmaf(q[i * 8 + 7], f3.y, acc);
            }
            s[ka] = (msk_f[res * 4 + ka] != 0.f) ? acc : -1e30f;
        }
        const float mx = fmaxf(fmaxf(s[0], s[1]), fmaxf(s[2], s[3]));
        float p[4], ps = 0.f;
#pragma unroll
        for (int ka = 0; ka < 4; ++ka) { p[ka] = __expf(s[ka] - mx); ps += p[ka]; }
        const float inv = 1.f / ps;

#pragma unroll
        for (int d = 0; d < 32; ++d) y[d] = 0.f;
#pragma unroll
        for (int ka = 0; ka < 4; ++ka) {
            const float pw = p[ka] * inv;
            const char* vp = sm + XH + (res * 4 + ka) * RS + hh * 64;
#pragma unroll
            for (int i = 0; i < 4; ++i) {
                uint4 u = *(const uint4*)(vp + i * 16);
                float2 f0 = __half22float2(*(__half2*)&u.x);
                float2 f1 = __half22float2(*(__half2*)&u.y);
                float2 f2 = __half22float2(*(__half2*)&u.z);
                float2 f3 = __half22float2(*(__half2*)&u.w);
                y[i * 8 + 0] = fmaf(pw, f0.x, y[i * 8 + 0]);
                y[i * 8 + 1] = fmaf(pw, f0.y, y[i * 8 + 1]);
                y[i * 8 + 2] = fmaf(pw, f1.x, y[i * 8 + 2]);
                y[i * 8 + 3] = fmaf(pw, f1.y, y[i * 8 + 3]);
                y[i * 8 + 4] = fmaf(pw, f2.x, y[i * 8 + 4]);
                y[i * 8 + 5] = fmaf(pw, f2.y, y[i * 8 + 5]);
                y[i * 8 + 6] = fmaf(pw, f3.x, y[i * 8 + 6]);
                y[i * 8 + 7] = fmaf(pw, f3.y, y[i * 8 + 7]);
            }
        }
    }
    __syncthreads();                          // (7) Q reads done before Y overwrite

    // ---- write Y fp16 -> QHO; wait Wo ----
    {
#pragma unroll
        for (int i = 0; i < 4; ++i) {
            uint4 hv;
            uint32_t* hp = &hv.x;
#pragma unroll
            for (int gidx = 0; gidx < 4; ++gidx) {
                __half2 h = __floats2half2_rn(y[i * 8 + gidx * 2], y[i * 8 + gidx * 2 + 1]);
                hp[gidx] = *(uint32_t*)&h;
            }
            *(uint4*)(sm + QHO + tq * RS + hh * 64 + i * 16) = hv;
        }
    }
    CPA_WAIT0();                              // Wo staged
    __syncthreads();                          // (8) Y visible

    // ---- P4: O GEMM (A=Y in QHO, B=Wo in W): out = Y·Wo^T + bo ----
    {
        load_a(sb + QHO, r0, lane, af);
        float d[2][4][4] = {};
        warp_gemm_c(af, sb + W, nc0, d, lane);
#pragma unroll
        for (int mi = 0; mi < 2; ++mi) {
            const int ra = r0 + mi * 16 + rq, rb = ra + 8;
            const float rma = rm_f[ra], rmb = rm_f[rb];
#pragma unroll
            for (int j = 0; j < 4; ++j) {
                const int col = nc0 + (j >> 1) * 16 + (j & 1) * 8 + c2;
                const float b0 = g_bias[3][col], b1 = g_bias[3][col + 1];
                float2 va, vb;
                va.x = (d[mi][j][0] + b0) * rma; va.y = (d[mi][j][1] + b1) * rma;
                vb.x = (d[mi][j][2] + b0) * rmb; vb.y = (d[mi][j][3] + b1) * rmb;
                *(float2*)(out + (tok0 + ra) * C + col) = va;
                *(float2*)(out + (tok0 + rb) * C + col) = vb;
            }
        }
    }
}

extern "C" void kernel_launch(void* const* d_in, const int* in_sizes, int n_in,
                              void* d_out, int out_size)
{
    const float* x    = (const float*)d_in[0];
    const int*   mask = (const int*)d_in[1];
    const float* Wq = (const float*)d_in[2];
    const float* bq = (const float*)d_in[3];
    const float* Wk = (const float*)d_in[4];
    const float* bk = (const float*)d_in[5];
    const float* Wv = (const float*)d_in[6];
    const float* bv = (const float*)d_in[7];
    const float* Wo = (const float*)d_in[8];
    const float* bo = (const float*)d_in[9];
    float* out = (float*)d_out;

    const int ntok = in_sizes[0] / laa::C;      // 262144
    const int nblk = ntok / laa::TOKS;          // 4096

    prep_split<<<32, 256>>>(Wq, bq, Wk, bk, Wv, bv, Wo, bo);

    cudaFuncSetAttribute(laa_mma_kernel,
                         cudaFuncAttributeMaxDynamicSharedMemorySize, laa::TOTAL);
    laa_mma_kernel<<<nblk, laa::NT, laa::TOTAL>>>(x, mask, out);
}

// round 12
// speedup vs baseline: 1.3588x; 1.0239x over previous
#include <cuda_runtime.h>
#include <cuda_fp16.h>
#include <cstdint>

// LocalAtomAttention (round 12): round-11 + tensor-core attention.
// S = Q·K^T diagonal tiles via mma; softmax in registers (S-accum layout ==
// A-fragment layout); P (fp16) feeds P·V mma with V via ldmatrix.trans.
// mma.sync fp16, 32x32 warp GEMM tiles, A-fragments cached across Q/K/V,
// W staged to dead smem regions via cp.async, 64-tok CTAs, 2 CTAs/SM.

namespace laa {
constexpr int C = 128, TOKS = 64, NT = 256;
constexpr uint32_t RS = 272;            // smem row stride bytes
constexpr uint32_t XH = 0, QHO = 17408, KHO = 34816 /*Wk then K*/,
                   W = 69632, MSK = 104448, RM = 104704,
                   TOTAL = 104960;      // x2 CTAs = 209,920 <= 228KB/SM
constexpr float SCALE = 0.17677669529663687f;  // 1/sqrt(32)
}

// Prepped fp16 weights: [4] = {Wq*s, Wk, Wv, Wo}, 272B rows, 34816B each.
__device__ __align__(16) unsigned char g_wimg[4][34816];
__device__ float g_bias[4][128];   // {bq*s, bk, bv, bo}

// ---------------- helpers ----------------
__device__ __forceinline__ uint32_t smem_u32(const void* p) {
    uint32_t a;
    asm("{ .reg .u64 t; cvta.to.shared.u64 t, %1; cvt.u32.u64 %0, t; }" : "=r"(a) : "l"(p));
    return a;
}
__device__ __forceinline__ void ldsm4(uint32_t& a0, uint32_t& a1, uint32_t& a2,
                                      uint32_t& a3, uint32_t addr) {
    asm volatile("ldmatrix.sync.aligned.m8n8.x4.shared.b16 {%0,%1,%2,%3}, [%4];"
                 : "=r"(a0), "=r"(a1), "=r"(a2), "=r"(a3) : "r"(addr));
}
__device__ __forceinline__ void ldsm4t(uint32_t& a0, uint32_t& a1, uint32_t& a2,
                                       uint32_t& a3, uint32_t addr) {
    asm volatile("ldmatrix.sync.aligned.m8n8.x4.trans.shared.b16 {%0,%1,%2,%3}, [%4];"
                 : "=r"(a0), "=r"(a1), "=r"(a2), "=r"(a3) : "r"(addr));
}
__device__ __forceinline__ void mma16816(float d[4], uint32_t a0, uint32_t a1,
                                         uint32_t a2, uint32_t a3,
                                         uint32_t b0, uint32_t b1) {
    asm volatile(
        "mma.sync.aligned.m16n8k16.row.col.f32.f16.f16.f32 "
        "{%0,%1,%2,%3}, {%4,%5,%6,%7}, {%8,%9}, {%0,%1,%2,%3};"
        : "+f"(d[0]), "+f"(d[1]), "+f"(d[2]), "+f"(d[3])
        : "r"(a0), "r"(a1), "r"(a2), "r"(a3), "r"(b0), "r"(b1));
}
__device__ __forceinline__ void cpa16(uint32_t dst, const unsigned char* src) {
    uint64_t g;
    asm("cvta.to.global.u64 %0, %1;" : "=l"(g) : "l"(src));
    asm volatile("cp.async.cg.shared.global [%0], [%1], 16;" :: "r"(dst), "l"(g));
}
#define CPA_COMMIT() asm volatile("cp.async.commit_group;" ::: "memory")
#define CPA_WAIT0()  asm volatile("cp.async.wait_group 0;" ::: "memory")

// ---------------- prep kernel (32 blocks: 4 matrices x 8 chunks) ----------------
__global__ void prep_split(const float* __restrict__ Wq, const float* __restrict__ bq,
                           const float* __restrict__ Wk, const float* __restrict__ bk,
                           const float* __restrict__ Wv, const float* __restrict__ bv,
                           const float* __restrict__ Wo, const float* __restrict__ bo) {
    const int m = blockIdx.x >> 3;
    const int chunk = blockIdx.x & 7;
    const float* src  = (m == 0) ? Wq : (m == 1) ? Wk : (m == 2) ? Wv : Wo;
    const float* bsrc = (m == 0) ? bq : (m == 1) ? bk : (m == 2) ? bv : bo;
    const float sc = (m == 0) ? laa::SCALE : 1.f;
    unsigned char* img = g_wimg[m];
    for (int i = chunk * 2048 + threadIdx.x; i < (chunk + 1) * 2048; i += blockDim.x) {
        int row = i >> 7, col = i & 127;
        *(__half*)(img + row * laa::RS + col * 2) = __float2half_rn(src[i] * sc);
    }
    if (chunk == 0 && threadIdx.x < 128)
        g_bias[m][threadIdx.x] = bsrc[threadIdx.x] * sc;
}

// ---------------- main kernel ----------------
using namespace laa;

// Load A fragments for a 32-row warp tile over K=128: 16 ldsm4 -> 64 regs.
__device__ __forceinline__ void load_a(uint32_t a_t, int r0, int lane, uint32_t* af) {
    const uint32_t aoff = (uint32_t)(r0 + (lane & 15)) * RS + ((lane >> 4) << 4);
#pragma unroll
    for (int ks = 0; ks < 8; ++ks) {
        ldsm4(af[ks*8+0], af[ks*8+1], af[ks*8+2], af[ks*8+3], a_t + aoff + ks * 32);
        ldsm4(af[ks*8+4], af[ks*8+5], af[ks*8+6], af[ks*8+7], a_t + aoff + 16 * RS + ks * 32);
    }
}

// Warp GEMM with cached A: D[32x32] += A·B^T, B fragments via ldsm from smem.
__device__ __forceinline__ void warp_gemm_c(const uint32_t* af, uint32_t wbuf,
                                            int nc0, float d[2][4][4], int lane) {
    const uint32_t brow = (lane & 7) + ((lane & 16) >> 1);
    const uint32_t bkof = (lane & 8) << 1;
#pragma unroll
    for (int ks = 0; ks < 8; ++ks) {
        const uint32_t kb = ks * 32;
        const uint32_t* a = af + ks * 8;
#pragma unroll
        for (int np = 0; np < 2; ++np) {
            const uint32_t ba = (uint32_t)(nc0 + np * 16 + brow) * RS + bkof + kb;
            uint32_t b0, b1, b2, b3;
            ldsm4(b0, b1, b2, b3, wbuf + ba);
            mma16816(d[0][2 * np],     a[0], a[1], a[2], a[3], b0, b1);
            mma16816(d[0][2 * np + 1], a[0], a[1], a[2], a[3], b2, b3);
            mma16816(d[1][2 * np],     a[4], a[5], a[6], a[7], b0, b1);
            mma16816(d[1][2 * np + 1], a[4], a[5], a[6], a[7], b2, b3);
        }
    }
}

// Stage full W matrix m (34816 B) into dst via cp.async.
__device__ __forceinline__ void stage_w(uint32_t dst, int m, int tid) {
    const unsigned char* src = g_wimg[m];
#pragma unroll 2
    for (int i = tid; i < 2176; i += NT) cpa16(dst + i * 16, src + i * 16);
    CPA_COMMIT();
}

__global__ __launch_bounds__(NT, 2)
void laa_mma_kernel(const float* __restrict__ x, const int* __restrict__ mask,
                    float* __restrict__ out)
{
    extern __shared__ __align__(16) char sm[];
    const uint32_t sb = smem_u32(sm);
    const int tid = threadIdx.x, lane = tid & 31, w = tid >> 5;
    const long long tok0 = (long long)blockIdx.x * TOKS;

    float* msk_f = (float*)(sm + MSK);
    float* rm_f  = (float*)(sm + RM);

    // ---- P-1: stage Wq->W and Wk->KHO; X load + fp16 convert; masks ----
    stage_w(sb + W, 0, tid);
    stage_w(sb + KHO, 1, tid);
#pragma unroll
    for (int it = 0; it < 8; ++it) {
        int idx = it * NT + tid;              // float4 index over [64][32]
        int row = idx >> 5, c4 = idx & 31;
        float4 v = __ldg((const float4*)x + (tok0 + row) * 32 + c4);
        __half2 h01 = __floats2half2_rn(v.x, v.y);
        __half2 h23 = __floats2half2_rn(v.z, v.w);
        uint2 hv;
        hv.x = *(uint32_t*)&h01; hv.y = *(uint32_t*)&h23;
        *(uint2*)(sm + XH + row * RS + c4 * 8) = hv;
    }
    if (tid < TOKS) {
        msk_f[tid] = (__ldg(&mask[tok0 + tid]) != 0) ? 1.f : 0.f;
        long long b = tok0 + (tid & ~3);
        int any = __ldg(&mask[b]) | __ldg(&mask[b + 1]) | __ldg(&mask[b + 2]) | __ldg(&mask[b + 3]);
        rm_f[tid] = (any != 0) ? 1.f : 0.f;
    }
    CPA_WAIT0();
    __syncthreads();                          // (1) X, Wq, Wk visible

    const int r0 = (w >> 2) * 32;             // {0,32}
    const int nc0 = (w & 3) * 32;             // {0,32,64,96}
    const int rq = lane >> 2;
    const int c2 = 2 * (lane & 3);

    // ---- cache A fragments of X once (reused by Q, K, V GEMMs) ----
    uint32_t af[64];
    load_a(sb + XH, r0, lane, af);

    // ---- P0: Q GEMM -> QHO fp16 ----
    {
        float d[2][4][4] = {};
        warp_gemm_c(af, sb + W, nc0, d, lane);
#pragma unroll
        for (int mi = 0; mi < 2; ++mi) {
            const int ra = r0 + mi * 16 + rq, rb = ra + 8;
#pragma unroll
            for (int j = 0; j < 4; ++j) {
                const int col = nc0 + (j >> 1) * 16 + (j & 1) * 8 + c2;
                const float b0 = g_bias[0][col], b1 = g_bias[0][col + 1];
                *(__half2*)(sm + QHO + ra * RS + col * 2) =
                    __floats2half2_rn(d[mi][j][0] + b0, d[mi][j][1] + b1);
                *(__half2*)(sm + QHO + rb * RS + col * 2) =
                    __floats2half2_rn(d[mi][j][2] + b0, d[mi][j][3] + b1);
            }
        }
    }
    __syncthreads();                          // (2) Wq reads done, Q visible

    // ---- P1: stage Wv->W; K GEMM (B=Wk in KHO); write K->KHO ----
    stage_w(sb + W, 2, tid);
    {
        float d[2][4][4] = {};
        warp_gemm_c(af, sb + KHO, nc0, d, lane);
        __syncthreads();                      // (3) all Wk reads done
#pragma unroll
        for (int mi = 0; mi < 2; ++mi) {
            const int ra = r0 + mi * 16 + rq, rb = ra + 8;
#pragma unroll
            for (int j = 0; j < 4; ++j) {
                const int col = nc0 + (j >> 1) * 16 + (j & 1) * 8 + c2;
                const float b0 = g_bias[1][col], b1 = g_bias[1][col + 1];
                *(__half2*)(sm + KHO + ra * RS + col * 2) =
                    __floats2half2_rn(d[mi][j][0] + b0, d[mi][j][1] + b1);
                *(__half2*)(sm + KHO + rb * RS + col * 2) =
                    __floats2half2_rn(d[mi][j][2] + b0, d[mi][j][3] + b1);
            }
        }
    }
    CPA_WAIT0();                              // Wv staged
    __syncthreads();                          // (4) K visible, Wv ready

    // ---- P2: V GEMM (B=Wv in W); stage Wo; write V->XH (X dead) ----
    {
        float d[2][4][4] = {};
        warp_gemm_c(af, sb + W, nc0, d, lane);
        __syncthreads();                      // (5) Wv reads done
        stage_w(sb + W, 3, tid);              // Wo staging hides behind attention
#pragma unroll
        for (int mi = 0; mi < 2; ++mi) {
            const int ra = r0 + mi * 16 + rq, rb = ra + 8;
#pragma unroll
            for (int j = 0; j < 4; ++j) {
                const int col = nc0 + (j >> 1) * 16 + (j & 1) * 8 + c2;
                const float b0 = g_bias[2][col], b1 = g_bias[2][col + 1];
                *(__half2*)(sm + XH + ra * RS + col * 2) =
                    __floats2half2_rn(d[mi][j][0] + b0, d[mi][j][1] + b1);
                *(__half2*)(sm + XH + rb * RS + col * 2) =
                    __floats2half2_rn(d[mi][j][2] + b0, d[mi][j][3] + b1);
            }
        }
    }
    __syncthreads();                          // (6) V visible

    // ---- P3: attention via tensor cores ----
    // Task = (head h, 16-token block mt); warp w handles tasks w and w+8.
    // S diagonal tiles: S_n0 (cols mt*16+0..7), S_n1 (cols mt*16+8..15).
    // Validity: thread's accum cols share the row's residue iff
    // (lane>>4)&1 == (lane>>1)&1  (same predicate for both row groups).
    float yacc[2][4][4] = {};                 // [task][dim-n-tile][4]
    const int valid = (((lane >> 4) & 1) == ((lane >> 1) & 1));
#pragma unroll
    for (int t = 0; t < 2; ++t) {
        const int task = w + t * 8;
        const int h = task >> 2, mt = task & 3;
        const uint32_t hb = (uint32_t)h * 64; // head byte offset
        const uint32_t rowa = (uint32_t)(mt * 16 + (lane & 15)) * RS + ((lane >> 4) << 4);

        // A = Q fragments (dims 0..31 of head), B = K fragments (same addressing;
        // pairs (r0,r2)=n-tile0, (r1,r3)=n-tile1 per k16 block)
        uint32_t qa[8], kb[8];
        ldsm4(qa[0], qa[1], qa[2], qa[3], sb + QHO + rowa + hb);
        ldsm4(qa[4], qa[5], qa[6], qa[7], sb + QHO + rowa + hb + 32);
        ldsm4(kb[0], kb[1], kb[2], kb[3], sb + KHO + rowa + hb);
        ldsm4(kb[4], kb[5], kb[6], kb[7], sb + KHO + rowa + hb + 32);

        float sn0[4] = {}, sn1[4] = {};
        mma16816(sn0, qa[0], qa[1], qa[2], qa[3], kb[0], kb[2]);
        mma16816(sn0, qa[4], qa[5], qa[6], qa[7], kb[4], kb[6]);
        mma16816(sn1, qa[0], qa[1], qa[2], qa[3], kb[1], kb[3]);
        mma16816(sn1, qa[4], qa[5], qa[6], qa[7], kb[5], kb[7]);

        // masked softmax in registers: row rq uses sn0[0..1]; row rq+8 uses sn1[2..3]
        const float mk0a = msk_f[mt * 16 + c2],     mk0b = msk_f[mt * 16 + c2 + 1];
        const float mk1a = msk_f[mt * 16 + 8 + c2], mk1b = msk_f[mt * 16 + 8 + c2 + 1];
        float s0 = (mk0a != 0.f) ? sn0[0] : -1e30f;
        float s1 = (mk0b != 0.f) ? sn0[1] : -1e30f;
        float u0 = (mk1a != 0.f) ? sn1[2] : -1e30f;
        float u1 = (mk1b != 0.f) ? sn1[3] : -1e30f;
        float rm0 = fmaxf(s0, s1), rm1 = fmaxf(u0, u1);
        rm0 = fmaxf(rm0, __shfl_xor_sync(0xffffffffu, rm0, 1));
        rm1 = fmaxf(rm1, __shfl_xor_sync(0xffffffffu, rm1, 1));
        float e0 = __expf(s0 - rm0), e1 = __expf(s1 - rm0);
        float f0 = __expf(u0 - rm1), f1 = __expf(u1 - rm1);
        float su0 = e0 + e1, su1 = f0 + f1;
        su0 += __shfl_xor_sync(0xffffffffu, su0, 1);
        su1 += __shfl_xor_sync(0xffffffffu, su1, 1);
        uint32_t pa0 = 0u, pa3 = 0u;
        if (valid) {
            const float i0 = 1.f / su0, i1 = 1.f / su1;
            __half2 hp0 = __floats2half2_rn(e0 * i0, e1 * i0);
            __half2 hp1 = __floats2half2_rn(f0 * i1, f1 * i1);
            pa0 = *(uint32_t*)&hp0;
            pa3 = *(uint32_t*)&hp1;
        }

        // P·V: B = V^T via ldmatrix.trans from token-major XH; pairs
        // (v0,v1)=dims+0..7, (v2,v3)=dims+8..15 per 16-dim block.
        uint32_t vb[8];
        ldsm4t(vb[0], vb[1], vb[2], vb[3], sb + XH + rowa + hb);
        ldsm4t(vb[4], vb[5], vb[6], vb[7], sb + XH + rowa + hb + 32);
        mma16816(yacc[t][0], pa0, 0u, 0u, pa3, vb[0], vb[1]);
        mma16816(yacc[t][1], pa0, 0u, 0u, pa3, vb[2], vb[3]);
        mma16816(yacc[t][2], pa0, 0u, 0u, pa3, vb[4], vb[5]);
        mma16816(yacc[t][3], pa0, 0u, 0u, pa3, vb[6], vb[7]);
    }
    __syncthreads();                          // (7) all Q/K/V reads done

    // ---- write Y fp16 -> QHO ----
#pragma unroll
    for (int t = 0; t < 2; ++t) {
        const int task = w + t * 8;
        const int h = task >> 2, mt = task & 3;
        const int ra = mt * 16 + rq, rb = ra + 8;
#pragma unroll
        for (int nt = 0; nt < 4; ++nt) {
            const int col = h * 32 + nt * 8 + c2;
            *(__half2*)(sm + QHO + ra * RS + col * 2) =
                __floats2half2_rn(yacc[t][nt][0], yacc[t][nt][1]);
            *(__half2*)(sm + QHO + rb * RS + col * 2) =
                __floats2half2_rn(yacc[t][nt][2], yacc[t][nt][3]);
        }
    }
    CPA_WAIT0();                              // Wo staged
    __syncthreads();                          // (8) Y visible

    // ---- P4: O GEMM (A=Y in QHO, B=Wo in W): out = Y·Wo^T + bo ----
    {
        load_a(sb + QHO, r0, lane, af);
        float d[2][4][4] = {};
        warp_gemm_c(af, sb + W, nc0, d, lane);
#pragma unroll
        for (int mi = 0; mi < 2; ++mi) {
            const int ra = r0 + mi * 16 + rq, rb = ra + 8;
            const float rma = rm_f[ra], rmb = rm_f[rb];
#pragma unroll
            for (int j = 0; j < 4; ++j) {
                const int col = nc0 + (j >> 1) * 16 + (j & 1) * 8 + c2;
                const float b0 = g_bias[3][col], b1 = g_bias[3][col + 1];
                float2 va, vb;
                va.x = (d[mi][j][0] + b0) * rma; va.y = (d[mi][j][1] + b1) * rma;
                vb.x = (d[mi][j][2] + b0) * rmb; vb.y = (d[mi][j][3] + b1) * rmb;
                *(float2*)(out + (tok0 + ra) * C + col) = va;
                *(float2*)(out + (tok0 + rb) * C + col) = vb;
            }
        }
    }
}

extern "C" void kernel_launch(void* const* d_in, const int* in_sizes, int n_in,
                              void* d_out, int out_size)
{
    const float* x    = (const float*)d_in[0];
    const int*   mask = (const int*)d_in[1];
    const float* Wq = (const float*)d_in[2];
    const float* bq = (const float*)d_in[3];
    const float* Wk = (const float*)d_in[4];
    const float* bk = (const float*)d_in[5];
    const float* Wv = (const float*)d_in[6];
    const float* bv = (const float*)d_in[7];
    const float* Wo = (const float*)d_in[8];
    const float* bo = (const float*)d_in[9];
    float* out = (float*)d_out;

    const int ntok = in_sizes[0] / laa::C;      // 262144
    const int nblk = ntok / laa::TOKS;          // 4096

    prep_split<<<32, 256>>>(Wq, bq, Wk, bk, Wv, bv, Wo, bo);

    cudaFuncSetAttribute(laa_mma_kernel,
                         cudaFuncAttributeMaxDynamicSharedMemorySize, laa::TOTAL);
    laa_mma_kernel<<<nblk, laa::NT, laa::TOTAL>>>(x, mask, out);
}